// round 3
// baseline (speedup 1.0000x reference)
#include <cuda_runtime.h>

#define NS 512
#define NC 128
#define DIM 640
#define HOR 256
#define NB 148
#define NT 256

// ---------------- device scratch ----------------
static __device__ float g_V[NS*NS];
static __device__ float g_v[NS];
static __device__ float g_W[NS*DIM];      // W = V * F  (512 x 640)
static __device__ float g_Q[DIM*DIM];
static __device__ float g_q[DIM];
static __device__ float g_zv[NS];         // V f + v
static __device__ float g_Lsym[NC*NC];    // L + L^T (strict parts), diag = L_jj
static __device__ float g_invd[NC];       // 1 / L[j][j]
static __device__ float g_K[NC*NS];
static __device__ float g_k[NC];
static __device__ float g_fVf, g_fv;
static __device__ float g_delta[HOR];
static __device__ unsigned g_count = 0;
static __device__ unsigned g_sense = 0;

#define MM16(a0,a1,a2,a3,bv) \
    acc[0][0] += (a0)*(bv).x; acc[0][1] += (a0)*(bv).y; acc[0][2] += (a0)*(bv).z; acc[0][3] += (a0)*(bv).w; \
    acc[1][0] += (a1)*(bv).x; acc[1][1] += (a1)*(bv).y; acc[1][2] += (a1)*(bv).z; acc[1][3] += (a1)*(bv).w; \
    acc[2][0] += (a2)*(bv).x; acc[2][1] += (a2)*(bv).y; acc[2][2] += (a2)*(bv).z; acc[2][3] += (a2)*(bv).w; \
    acc[3][0] += (a3)*(bv).x; acc[3][1] += (a3)*(bv).y; acc[3][2] += (a3)*(bv).z; acc[3][3] += (a3)*(bv).w;

// grid-wide sense-reversal barrier. __threadfence() on sm_103a emits CCTL.IVALL
// (gpu-scope), which both publishes our writes and invalidates stale L1 lines.
__device__ __forceinline__ void gbar(unsigned ph) {
    __syncthreads();
    if (threadIdx.x == 0) {
        __threadfence();
        if (atomicAdd(&g_count, 1u) == NB - 1u) {
            g_count = 0u;
            __threadfence();
            atomicExch(&g_sense, ph);
        } else {
            while (*(volatile unsigned*)&g_sense != ph) { }
            __threadfence();
        }
    }
    __syncthreads();
}

__global__ __launch_bounds__(NT, 1)
void lqr_persistent(const float* __restrict__ F, const float* __restrict__ f,
                    const float* __restrict__ C, const float* __restrict__ c,
                    float* __restrict__ out) {
    extern __shared__ float sh[];
    const int b = blockIdx.x;
    const int t = threadIdx.x;
    const int tx = t & 15, ty = t >> 4;

    // output layout: Ks | ks | Vs | vs | consts (each time-reversed)
    float* Ks_all = out;
    float* ks_all = out + (size_t)HOR*NC*NS;
    float* Vs_all = ks_all + (size_t)HOR*NC;
    float* vs_all = Vs_all + (size_t)HOR*NS*NS;
    float* co_all = vs_all + (size_t)HOR*NS;

    // phase counter continues from previous launch's g_sense (no cross-launch writes in between)
    unsigned phase = *(volatile unsigned*)&g_sense;

    // ---- init: V = C[:n,:n], v = c[:n] ----
    for (int idx = b*NT + t; idx < NS*NS; idx += NB*NT)
        g_V[idx] = C[(idx >> 9)*DIM + (idx & 511)];
    for (int idx = b*NT + t; idx < NS; idx += NB*NT)
        g_v[idx] = c[idx];
    gbar(++phase);

    for (int step = 0; step < HOR; step++) {
        const int slot = HOR - 1 - step;

        // ================= Phase A: W = V*F ; zv = V f + v =================
        if (b < 80) {
            float* As = sh;            // [16][65]
            float* Bs = sh + 16*65;    // [16][64]
            int r0 = (b/10)*64, c0 = (b%10)*64;
            float acc[4][4] = {};
            int kk = t & 15, rr = t >> 4;
            for (int k0 = 0; k0 < NS; k0 += 16) {
                #pragma unroll
                for (int i = 0; i < 4; i++)
                    As[kk*65 + rr + i*16] = g_V[(r0+rr+i*16)*NS + k0 + kk];
                #pragma unroll
                for (int i = 0; i < 4; i++) {
                    int e = t + i*256;
                    Bs[(e>>6)*64 + (e&63)] = F[(k0+(e>>6))*DIM + c0 + (e&63)];
                }
                __syncthreads();
                #pragma unroll
                for (int k2 = 0; k2 < 16; k2++) {
                    float a0 = As[k2*65+ty*4+0], a1 = As[k2*65+ty*4+1],
                          a2 = As[k2*65+ty*4+2], a3 = As[k2*65+ty*4+3];
                    float4 bv = *(const float4*)&Bs[k2*64 + tx*4];
                    MM16(a0, a1, a2, a3, bv)
                }
                __syncthreads();
            }
            #pragma unroll
            for (int i = 0; i < 4; i++)
                #pragma unroll
                for (int j = 0; j < 4; j++)
                    g_W[(r0+ty*4+i)*DIM + c0 + tx*4 + j] = acc[i][j];
        } else if (b < 88) {
            // zv[i] = sum_k V[i][k] f[k] + v[i]
            int i = (b-80)*64 + (t >> 2);
            int l4 = t & 3;
            const float* row = &g_V[i*NS];
            float s = 0.f;
            for (int k = l4*128; k < l4*128 + 128; k++) s += row[k]*f[k];
            s += __shfl_xor_sync(0xffffffffu, s, 1);
            s += __shfl_xor_sync(0xffffffffu, s, 2);
            if (l4 == 0) g_zv[i] = s + g_v[i];
        }
        gbar(++phase);

        // ================= Phase B: Q = C + F^T W ; q = c + F^T zv ; scalars =================
        if (b < 100) {
            float* As = sh;            // [16][64]
            float* Bs = sh + 1024;     // [16][64]
            int r0 = (b/10)*64, c0 = (b%10)*64;
            float acc[4][4] = {};
            for (int k0 = 0; k0 < NS; k0 += 16) {
                #pragma unroll
                for (int i = 0; i < 4; i++) {
                    int e = t + i*256;
                    As[e] = F[(k0+(e>>6))*DIM + r0 + (e&63)];
                    Bs[e] = g_W[(k0+(e>>6))*DIM + c0 + (e&63)];
                }
                __syncthreads();
                #pragma unroll
                for (int k2 = 0; k2 < 16; k2++) {
                    float4 av = *(const float4*)&As[k2*64 + ty*4];
                    float4 bv = *(const float4*)&Bs[k2*64 + tx*4];
                    MM16(av.x, av.y, av.z, av.w, bv)
                }
                __syncthreads();
            }
            #pragma unroll
            for (int i = 0; i < 4; i++)
                #pragma unroll
                for (int j = 0; j < 4; j++) {
                    int gi = r0+ty*4+i, gj = c0+tx*4+j;
                    g_Q[gi*DIM+gj] = C[gi*DIM+gj] + acc[i][j];
                }
        } else if (b < 110) {
            int o = (b-100)*64 + (t >> 2);
            int l4 = t & 3;
            float s = 0.f;
            for (int k = l4*128; k < l4*128 + 128; k++) s += F[k*DIM + o]*g_zv[k];
            s += __shfl_xor_sync(0xffffffffu, s, 1);
            s += __shfl_xor_sync(0xffffffffu, s, 2);
            if (l4 == 0) g_q[o] = c[o] + s;
        } else if (b == 110) {
            // fVf = f.(zv - v), fv = f.v
            float s1 = 0.f, s2 = 0.f;
            for (int i = t; i < NS; i += NT) {
                float fi = f[i], vi = g_v[i];
                s1 += fi*(g_zv[i] - vi);
                s2 += fi*vi;
            }
            float* red = sh;
            red[t] = s1; __syncthreads();
            for (int st = 128; st > 0; st >>= 1) { if (t < st) red[t] += red[t+st]; __syncthreads(); }
            if (t == 0) g_fVf = red[0];
            __syncthreads();
            red[t] = s2; __syncthreads();
            for (int st = 128; st > 0; st >>= 1) { if (t < st) red[t] += red[t+st]; __syncthreads(); }
            if (t == 0) g_fv = red[0];
        }
        gbar(++phase);

        // ================= Phase C: Cholesky of Quu (CTA 0, in smem) =================
        if (b == 0) {
            float* shQ = sh;   // [128][129]
            for (int idx = t; idx < NC*NC; idx += NT)
                shQ[(idx>>7)*129 + (idx&127)] = g_Q[(NS+(idx>>7))*DIM + NS + (idx&127)];
            __syncthreads();
            for (int j = 0; j < NC; j++) {
                float d = shQ[j*129+j];
                float invs = rsqrtf(d);
                if (t < NC-j) shQ[(j+t)*129 + j] *= invs;   // includes diag -> sqrt(d)
                if (t == 0) g_invd[j] = invs;
                __syncthreads();
                int i = j + 1 + (t >> 1);
                if (i < NC) {
                    float lij = shQ[i*129 + j];
                    int kbeg = j+1, kend = i;
                    int len = kend - kbeg + 1;
                    int mid = kbeg + ((len+1) >> 1);
                    int ka = (t&1) ? mid : kbeg;
                    int kb = (t&1) ? kend+1 : mid;
                    for (int k = ka; k < kb; k++)
                        shQ[i*129+k] -= lij * shQ[k*129+j];
                }
                __syncthreads();
            }
            // write symmetrized L
            for (int idx = t; idx < NC*NC; idx += NT) {
                int row = idx >> 7, col = idx & 127;
                if (col <= row) {
                    float val = shQ[row*129 + col];
                    g_Lsym[row*NC + col] = val;
                    g_Lsym[col*NC + row] = val;
                }
            }
        }
        gbar(++phase);

        // ================= Phase D: solve Quu X = -[Qux | qu] =================
        if (b < 65) {
            float* T      = sh;            // 128x128 symmetrized L
            float* invd_s = sh + NC*NC;
            for (int idx = t; idx < NC*NC; idx += NT) T[idx] = g_Lsym[idx];
            if (t < NC) invd_s[t] = g_invd[t];
            __syncthreads();
            int warp = t >> 5, lane = t & 31;
            int col = b*8 + warp;
            if (col <= NS) {
                float r0, r1, r2, r3;
                if (col < NS) {
                    r0 = -g_Q[(NS+lane     )*DIM + col];
                    r1 = -g_Q[(NS+lane + 32)*DIM + col];
                    r2 = -g_Q[(NS+lane + 64)*DIM + col];
                    r3 = -g_Q[(NS+lane + 96)*DIM + col];
                } else {
                    r0 = -g_q[NS+lane]; r1 = -g_q[NS+lane+32];
                    r2 = -g_q[NS+lane+64]; r3 = -g_q[NS+lane+96];
                }
                // forward: L y = b   (T[i][l], l>i holds L[l][i])
                #pragma unroll 1
                for (int i = 0; i < NC; i++) {
                    int si = i >> 5, li = i & 31;
                    float mv = (si == 0) ? r0 : ((si == 1) ? r1 : ((si == 2) ? r2 : r3));
                    float y = __shfl_sync(0xffffffffu, mv, li) * invd_s[i];
                    const float* Ti = T + i*NC;
                    if (lane      > i) r0 -= Ti[lane     ]*y; else if (lane      == i) r0 = y;
                    if (lane + 32 > i) r1 -= Ti[lane + 32]*y; else if (lane + 32 == i) r1 = y;
                    if (lane + 64 > i) r2 -= Ti[lane + 64]*y; else if (lane + 64 == i) r2 = y;
                    if (lane + 96 > i) r3 -= Ti[lane + 96]*y; else if (lane + 96 == i) r3 = y;
                }
                // backward: L^T x = y   (T[i][l], l<i holds L[i][l])
                #pragma unroll 1
                for (int i = NC-1; i >= 0; i--) {
                    int si = i >> 5, li = i & 31;
                    float mv = (si == 0) ? r0 : ((si == 1) ? r1 : ((si == 2) ? r2 : r3));
                    float x = __shfl_sync(0xffffffffu, mv, li) * invd_s[i];
                    const float* Ti = T + i*NC;
                    if (lane      < i) r0 -= Ti[lane     ]*x; else if (lane      == i) r0 = x;
                    if (lane + 32 < i) r1 -= Ti[lane + 32]*x; else if (lane + 32 == i) r1 = x;
                    if (lane + 64 < i) r2 -= Ti[lane + 64]*x; else if (lane + 64 == i) r2 = x;
                    if (lane + 96 < i) r3 -= Ti[lane + 96]*x; else if (lane + 96 == i) r3 = x;
                }
                if (col < NS) {
                    float* Ko = Ks_all + (size_t)slot*NC*NS;
                    g_K[(lane     )*NS + col] = r0;  Ko[(lane     )*NS + col] = r0;
                    g_K[(lane + 32)*NS + col] = r1;  Ko[(lane + 32)*NS + col] = r1;
                    g_K[(lane + 64)*NS + col] = r2;  Ko[(lane + 64)*NS + col] = r2;
                    g_K[(lane + 96)*NS + col] = r3;  Ko[(lane + 96)*NS + col] = r3;
                } else {
                    float* ko = ks_all + (size_t)slot*NC;
                    g_k[lane]      = r0;  ko[lane]      = r0;
                    g_k[lane + 32] = r1;  ko[lane + 32] = r1;
                    g_k[lane + 64] = r2;  ko[lane + 64] = r2;
                    g_k[lane + 96] = r3;  ko[lane + 96] = r3;
                }
            }
        }
        gbar(++phase);

        // ================= Phase E: Vn = Qxx + Qxu K ; vn = qx + Qxu k ; delta =================
        if (b < 64) {
            float* As = sh;            // [16][65] transposed Qxu tile
            float* Bs = sh + 16*65;    // [16][64]
            int r0 = (b>>3)*64, c0 = (b&7)*64;
            float acc[4][4] = {};
            int kk = t & 15, rr = t >> 4;
            for (int k0 = 0; k0 < NC; k0 += 16) {
                #pragma unroll
                for (int i = 0; i < 4; i++)
                    As[kk*65 + rr + i*16] = g_Q[(r0+rr+i*16)*DIM + NS + k0 + kk];
                #pragma unroll
                for (int i = 0; i < 4; i++) {
                    int e = t + i*256;
                    Bs[(e>>6)*64 + (e&63)] = g_K[(k0+(e>>6))*NS + c0 + (e&63)];
                }
                __syncthreads();
                #pragma unroll
                for (int k2 = 0; k2 < 16; k2++) {
                    float a0 = As[k2*65+ty*4+0], a1 = As[k2*65+ty*4+1],
                          a2 = As[k2*65+ty*4+2], a3 = As[k2*65+ty*4+3];
                    float4 bv = *(const float4*)&Bs[k2*64 + tx*4];
                    MM16(a0, a1, a2, a3, bv)
                }
                __syncthreads();
            }
            float* Vo = Vs_all + (size_t)slot*NS*NS;
            #pragma unroll
            for (int i = 0; i < 4; i++)
                #pragma unroll
                for (int j = 0; j < 4; j++) {
                    int gi = r0+ty*4+i, gj = c0+tx*4+j;
                    float val = g_Q[gi*DIM+gj] + acc[i][j];
                    g_V[gi*NS+gj] = val;
                    Vo[gi*NS+gj]  = val;
                }
        } else if (b < 72) {
            int i = (b-64)*64 + (t >> 2);
            int l4 = t & 3;
            const float* row = &g_Q[i*DIM + NS];
            float s = 0.f;
            for (int a = l4*32; a < l4*32 + 32; a++) s += row[a]*g_k[a];
            s += __shfl_xor_sync(0xffffffffu, s, 1);
            s += __shfl_xor_sync(0xffffffffu, s, 2);
            if (l4 == 0) {
                float val = g_q[i] + s;
                g_v[i] = val;
                vs_all[(size_t)slot*NS + i] = val;
            }
        } else if (b == 72) {
            float* red = sh;
            float s = (t < NC) ? g_k[t]*g_q[NS+t] : 0.f;
            red[t] = s; __syncthreads();
            for (int st = 128; st > 0; st >>= 1) { if (t < st) red[t] += red[t+st]; __syncthreads(); }
            if (t == 0) g_delta[step] = 0.5f*red[0] + 0.5f*g_fVf + g_fv;
        }
        gbar(++phase);
    }

    // ---- consts prefix (reversed) ----
    if (b == 0 && t == 0) {
        float run = 0.f;
        for (int i = 0; i < HOR; i++) {
            run += g_delta[i];
            co_all[HOR-1-i] = run;
        }
    }
}

extern "C" void kernel_launch(void* const* d_in, const int* in_sizes, int n_in,
                              void* d_out, int out_size) {
    const float* F = (const float*)d_in[0];
    const float* f = (const float*)d_in[1];
    const float* C = (const float*)d_in[2];
    const float* c = (const float*)d_in[3];
    float* out = (float*)d_out;

    const int SMEM = (NC*NC + NC) * 4;   // 66048 B (chol needs 128*129*4 = same)
    static_assert(NC*NC + NC == 128*129, "smem sizing");
    cudaFuncSetAttribute(lqr_persistent, cudaFuncAttributeMaxDynamicSharedMemorySize, SMEM);

    lqr_persistent<<<NB, NT, SMEM>>>(F, f, C, c, out);
}